// round 3
// baseline (speedup 1.0000x reference)
#include <cuda_runtime.h>
#include <cstdint>

// ---------------- problem constants ----------------
#define MTOK 256
#define KDIM 1024
#define NDIM 2048
#define EXP  64
#define TOPK 8
#define CAP  32            // (MTOK*TOPK)/EXP, balanced routing
#define LTOT (MTOK*TOPK)   // 2048

// ---------------- tiling ----------------
#define MT 128             // expert-weight rows per CTA (output cols)
#define NWARP 8
#define NTHR 256
#define CHUNK_K 32                     // k elems per cp.async stage
#define NCHUNK (KDIM/CHUNK_K)          // 32
#define STAGES 4
#define STAGE_BYTES (MT*CHUNK_K*4)     // 16384

// smem layout
#define OFF_LI 0                       // 32 ints (flat slot ids)
#define OFF_LW 128                     // 32 floats (routing weights)
#define SM_A   1024                    // token tiles in mma-fragment order
#define A_BYTES (CAP*KDIM*4)           // 131072
#define SM_B   (SM_A + A_BYTES)        // weight stages
#define SMEM_TOTAL (SM_B + STAGES*STAGE_BYTES)   // 197632

__device__ int g_list[EXP * CAP];

// ---------------- routing: stable per-expert slot lists ----------------
__global__ void route_kernel(const int* __restrict__ ids) {
    int e = blockIdx.x;
    int lane = threadIdx.x;
    int total = 0;
    for (int base = 0; base < LTOT; base += 32) {
        int id = ids[base + lane];
        unsigned m = __ballot_sync(0xffffffffu, id == e);
        if (id == e) {
            int slot = total + __popc(m & ((1u << lane) - 1u));
            g_list[e * CAP + slot] = base + lane;
        }
        total += __popc(m);
    }
}

// ---------------- helpers ----------------
__device__ __forceinline__ uint32_t smem_u32(const void* p) {
    uint32_t a;
    asm("{ .reg .u64 t; cvta.to.shared.u64 t, %1; cvt.u32.u64 %0, t; }" : "=r"(a) : "l"(p));
    return a;
}

__device__ __forceinline__ void cpa16(uint32_t dst, const void* src) {
    asm volatile("cp.async.cg.shared.global [%0], [%1], 16;"
                 :: "r"(dst), "l"(src) : "memory");
}

#define MMA_TF32(d, a0, a1, a2, a3, b0, b1)                                   \
    asm volatile(                                                             \
        "mma.sync.aligned.m16n8k8.row.col.f32.tf32.tf32.f32 "                 \
        "{%0,%1,%2,%3}, {%4,%5,%6,%7}, {%8,%9}, {%0,%1,%2,%3};"               \
        : "+f"(d[0]), "+f"(d[1]), "+f"(d[2]), "+f"(d[3])                      \
        : "r"(a0), "r"(a1), "r"(a2), "r"(a3), "r"(b0), "r"(b1))

// ---------------- main fused grouped-GEMM kernel ----------------
__global__ void __launch_bounds__(NTHR, 1)
moe_gemm_kernel(const float* __restrict__ A,
                const float* __restrict__ B,
                const float* __restrict__ bias,
                const float* __restrict__ tw,
                float* __restrict__ out) {
    extern __shared__ char smem[];
    const uint32_t sb = smem_u32(smem);
    const int tid  = threadIdx.x;
    const int w    = tid >> 5;
    const int lane = tid & 31;
    const int mt   = blockIdx.x;
    const int e    = blockIdx.y;

    // weight source base for this CTA: B[e][mt*128 .. +128][*]
    const float* Bsrc = B + ((size_t)e * NDIM + (size_t)mt * MT) * KDIM;

    // ---- kick off cp.async prologue FIRST (overlaps the A gather) ----
    #pragma unroll
    for (int c = 0; c < STAGES; ++c) {
        const uint32_t stage_base = sb + SM_B + c * STAGE_BYTES;
        #pragma unroll
        for (int i = 0; i < 4; ++i) {
            int id = tid + i * NTHR;
            int row = id >> 3, g = id & 7;
            cpa16(stage_base + row * 128 + ((g * 16) ^ ((row & 7) * 16)),
                  Bsrc + (size_t)row * KDIM + c * CHUNK_K + g * 4);
        }
        asm volatile("cp.async.commit_group;" ::: "memory");
    }

    // ---- routing lists ----
    int*   li_s = (int*)(smem + OFF_LI);
    float* lw_s = (float*)(smem + OFF_LW);
    if (tid < CAP) {
        int l = g_list[e * CAP + tid];
        li_s[tid] = l;
        lw_s[tid] = tw[l];
    }
    __syncthreads();

    // ---- gather token rows into SM_A, tf32-rounded, in mma B-fragment order
    // element (t, k) stored at:
    //   kb16 = k/16, f = t/8, j = (k%16)/4, slot = (4*(t%8) + k%4) ^ (kb16%8)
    //   byte = SM_A + ((kb16*4 + f)*32 + slot)*16 + j*4
    {
        const int kb16 = tid >> 2;           // k = tid*4
        const int j    = tid & 3;
        const int sw   = kb16 & 7;
        #pragma unroll 4
        for (int t = 0; t < CAP; ++t) {
            const int l = li_s[t];
            const float4 v = ((const float4*)(A + (size_t)(l >> 3) * KDIM))[tid];
            uint32_t r0, r1, r2, r3;
            asm("cvt.rna.tf32.f32 %0, %1;" : "=r"(r0) : "f"(v.x));
            asm("cvt.rna.tf32.f32 %0, %1;" : "=r"(r1) : "f"(v.y));
            asm("cvt.rna.tf32.f32 %0, %1;" : "=r"(r2) : "f"(v.z));
            asm("cvt.rna.tf32.f32 %0, %1;" : "=r"(r3) : "f"(v.w));
            const int f = t >> 3;
            const int sb4 = (t & 7) << 2;
            char* base = smem + SM_A + (((kb16 << 2) + f) << 9) + (j << 2);
            *(uint32_t*)(base + (((sb4 + 0) ^ sw) << 4)) = r0;
            *(uint32_t*)(base + (((sb4 + 1) ^ sw) << 4)) = r1;
            *(uint32_t*)(base + (((sb4 + 2) ^ sw) << 4)) = r2;
            *(uint32_t*)(base + (((sb4 + 3) ^ sw) << 4)) = r3;
        }
    }

    // ---- main loop: 16 iterations, 2 chunks (stages) each ----
    float acc[4][4] = {};                 // [token-frag][c0..c3]
    const int rlo = (w << 4) + (lane >> 2);      // weight row (mma M) 0..119
    const uint32_t swz = ((lane >> 2) & 7) << 4; // (rlo&7)*16

    for (int it = 0; it < 16; ++it) {
        if (it < 15) asm volatile("cp.async.wait_group 2;" ::: "memory");
        else         asm volatile("cp.async.wait_group 0;" ::: "memory");
        __syncthreads();

        #pragma unroll
        for (int half = 0; half < 2; ++half) {
            const int chunk = 2 * it + half;
            const char* stgp = smem + SM_B + (chunk & 3) * STAGE_BYTES + rlo * 128;
            #pragma unroll
            for (int kb = 0; kb < 2; ++kb) {
                const int kb16 = chunk * 2 + kb;
                uint4 bq[4];
                #pragma unroll
                for (int f = 0; f < 4; ++f)
                    bq[f] = *(const uint4*)(smem + SM_A +
                            ((((kb16 << 2) + f) << 5) + (lane ^ (kb16 & 7))) * 16);
                #pragma unroll
                for (int d8 = 0; d8 < 2; ++d8) {
                    const int cb = (kb << 4) + (d8 << 3) + (lane & 3);
                    const uint32_t x0 = ((uint32_t)(cb << 2)) ^ swz;
                    const uint32_t x1 = ((uint32_t)((cb + 4) << 2)) ^ swz;
                    uint32_t a0 = *(const uint32_t*)(stgp + x0);
                    uint32_t a1 = *(const uint32_t*)(stgp + 1024 + x0);
                    uint32_t a2 = *(const uint32_t*)(stgp + x1);
                    uint32_t a3 = *(const uint32_t*)(stgp + 1024 + x1);
                    if (d8 == 0) {
                        MMA_TF32(acc[0], a0, a1, a2, a3, bq[0].x, bq[0].y);
                        MMA_TF32(acc[1], a0, a1, a2, a3, bq[1].x, bq[1].y);
                        MMA_TF32(acc[2], a0, a1, a2, a3, bq[2].x, bq[2].y);
                        MMA_TF32(acc[3], a0, a1, a2, a3, bq[3].x, bq[3].y);
                    } else {
                        MMA_TF32(acc[0], a0, a1, a2, a3, bq[0].z, bq[0].w);
                        MMA_TF32(acc[1], a0, a1, a2, a3, bq[1].z, bq[1].w);
                        MMA_TF32(acc[2], a0, a1, a2, a3, bq[2].z, bq[2].w);
                        MMA_TF32(acc[3], a0, a1, a2, a3, bq[3].z, bq[3].w);
                    }
                }
            }
        }
        __syncthreads();

        #pragma unroll
        for (int half = 0; half < 2; ++half) {
            const int c = 2 * it + 4 + half;
            if (c < NCHUNK) {
                const uint32_t stage_base = sb + SM_B + (c & 3) * STAGE_BYTES;
                #pragma unroll
                for (int i = 0; i < 4; ++i) {
                    int id = tid + i * NTHR;
                    int row = id >> 3, g = id & 7;
                    cpa16(stage_base + row * 128 + ((g * 16) ^ ((row & 7) * 16)),
                          Bsrc + (size_t)row * KDIM + c * CHUNK_K + g * 4);
                }
                asm volatile("cp.async.commit_group;" ::: "memory");
            }
        }
    }

    // ---- epilogue: bias + routed weight, stage through smem for coalescing ----
    float* stg = (float*)(smem + SM_B);      // 32 x 132 floats (padded stride)
    const float bv0 = bias[e * NDIM + mt * MT + rlo];
    const float bv1 = bias[e * NDIM + mt * MT + rlo + 8];
    #pragma unroll
    for (int f = 0; f < 4; ++f) {
        const int t0 = (f << 3) + ((lane & 3) << 1);
        const float w0 = lw_s[t0], w1 = lw_s[t0 + 1];
        stg[t0 * 132 + rlo]           = (acc[f][0] + bv0) * w0;
        stg[(t0 + 1) * 132 + rlo]     = (acc[f][1] + bv0) * w1;
        stg[t0 * 132 + rlo + 8]       = (acc[f][2] + bv1) * w0;
        stg[(t0 + 1) * 132 + rlo + 8] = (acc[f][3] + bv1) * w1;
    }
    __syncthreads();

    #pragma unroll 4
    for (int i = tid; i < CAP * MT; i += NTHR) {
        const int t = i >> 7, n = i & 127;
        out[(size_t)li_s[t] * NDIM + mt * MT + n] = stg[t * 132 + n];
    }
}

// ---------------- host launch ----------------
extern "C" void kernel_launch(void* const* d_in, const int* in_sizes, int n_in,
                              void* d_out, int out_size) {
    const float* A    = (const float*)d_in[0];
    const float* B    = (const float*)d_in[1];
    const float* bias = (const float*)d_in[2];
    const float* tw   = (const float*)d_in[3];
    const int*   ids  = (const int*)d_in[4];
    float*       out  = (float*)d_out;

    static bool attr_set = false;
    if (!attr_set) {
        cudaFuncSetAttribute(moe_gemm_kernel,
                             cudaFuncAttributeMaxDynamicSharedMemorySize, SMEM_TOTAL);
        attr_set = true;
    }

    route_kernel<<<EXP, 32>>>(ids);
    dim3 grid(NDIM / MT, EXP);
    moe_gemm_kernel<<<grid, NTHR, SMEM_TOTAL>>>(A, B, bias, tw, out);
}

// round 7
// speedup vs baseline: 1.7069x; 1.7069x over previous
#include <cuda_runtime.h>
#include <cstdint>

// ---------------- problem constants ----------------
#define MTOK 256
#define KDIM 1024
#define NDIM 2048
#define EXP  64
#define TOPK 8
#define CAP  32            // (MTOK*TOPK)/EXP, balanced routing
#define LTOT (MTOK*TOPK)   // 2048

// ---------------- tiling ----------------
#define NTHR 256
#define MT 128                          // weight rows per tile
#define TILES_PER_CTA 8                 // 128 CTAs x 8 tiles = 1024 tiles
#define NCTA 128
#define CHUNK_K 32                      // k elems per stage chunk
#define CHUNKS_PER_TILE (KDIM/CHUNK_K)  // 32
#define CHUNKS_TOTAL (TILES_PER_CTA*CHUNKS_PER_TILE)  // 256
#define STAGES 4
#define STAGE_BYTES (MT*CHUNK_K*4)      // 16384

// smem layout
#define OFF_LI 0                        // 32 ints (flat slot ids)
#define OFF_LW 128                      // 32 floats (routing weights)
#define OFF_STG 1024                    // 32 x 132 floats epilogue staging (16896B)
#define SM_A   17920                    // token tiles in mma-fragment order
#define A_BYTES (CAP*KDIM*4)            // 131072
#define SM_B   (SM_A + A_BYTES)         // 148992
#define SMEM_TOTAL (SM_B + STAGES*STAGE_BYTES)   // 214528

// ---------------- helpers ----------------
__device__ __forceinline__ uint32_t smem_u32(const void* p) {
    uint32_t a;
    asm("{ .reg .u64 t; cvta.to.shared.u64 t, %1; cvt.u32.u64 %0, t; }" : "=r"(a) : "l"(p));
    return a;
}

__device__ __forceinline__ void cpa16(uint32_t dst, const void* src) {
    asm volatile("cp.async.cg.shared.global [%0], [%1], 16;"
                 :: "r"(dst), "l"(src) : "memory");
}

#define MMA_TF32(d, a0, a1, a2, a3, b0, b1)                                   \
    asm volatile(                                                             \
        "mma.sync.aligned.m16n8k8.row.col.f32.tf32.tf32.f32 "                 \
        "{%0,%1,%2,%3}, {%4,%5,%6,%7}, {%8,%9}, {%0,%1,%2,%3};"               \
        : "+f"(d[0]), "+f"(d[1]), "+f"(d[2]), "+f"(d[3])                      \
        : "r"(a0), "r"(a1), "r"(a2), "r"(a3), "r"(b0), "r"(b1))

// ---------------- persistent fused grouped-GEMM kernel ----------------
__global__ void __launch_bounds__(NTHR, 1)
moe_gemm_kernel(const float* __restrict__ A,
                const float* __restrict__ B,
                const float* __restrict__ bias,
                const float* __restrict__ tw,
                const int*   __restrict__ ids,
                float* __restrict__ out) {
    extern __shared__ char smem[];
    const uint32_t sb = smem_u32(smem);
    const int tid  = threadIdx.x;
    const int w    = tid >> 5;
    const int lane = tid & 31;
    const int cta  = blockIdx.x;
    const int e    = cta >> 1;        // expert
    const int half = cta & 1;         // which 1024-row half of B[e]

    // contiguous 4MB weight stream for this CTA
    const float* Bsrc = B + ((size_t)e * NDIM + (size_t)half * (TILES_PER_CTA * MT)) * KDIM;

    // ---- issue cp.async prologue (chunks 0..2) FIRST ----
    #pragma unroll
    for (int c = 0; c < STAGES - 1; ++c) {
        const int tilec = c >> 5, cc = c & 31;
        const uint32_t stage_base = sb + SM_B + (c & (STAGES - 1)) * STAGE_BYTES;
        #pragma unroll
        for (int i = 0; i < 4; ++i) {
            int id = tid + i * NTHR;
            int row = id >> 3, g = id & 7;
            cpa16(stage_base + row * 128 + ((g * 16) ^ ((row & 7) * 16)),
                  Bsrc + ((size_t)(tilec * MT + row)) * KDIM + cc * CHUNK_K + g * 4);
        }
        asm volatile("cp.async.commit_group;" ::: "memory");
    }

    // ---- in-kernel routing: warp 0 scans topk_ids (overlaps prologue) ----
    int*   li_s = (int*)(smem + OFF_LI);
    float* lw_s = (float*)(smem + OFF_LW);
    if (w == 0) {
        int total = 0;
        #pragma unroll
        for (int base = 0; base < LTOT; base += 32) {
            int id = __ldg(ids + base + lane);
            unsigned m = __ballot_sync(0xffffffffu, id == e);
            if (id == e) {
                int slot = total + __popc(m & ((1u << lane) - 1u));
                li_s[slot] = base + lane;
                lw_s[slot] = __ldg(tw + base + lane);
            }
            total += __popc(m);
        }
    }
    __syncthreads();

    // ---- gather token rows into SM_A, tf32-rounded, mma B-fragment order
    // element (t, k): kb16=k/16, f=t/8, j=(k%16)/4, slot=(4*(t%8)+k%4)^(kb16%8)
    // byte = SM_A + ((kb16*4+f)*32 + slot)*16 + j*4
    {
        const int kb16 = tid >> 2;           // k = tid*4
        const int j    = tid & 3;
        const int sw   = kb16 & 7;
        #pragma unroll 4
        for (int t = 0; t < CAP; ++t) {
            const int l = li_s[t];
            const float4 v = ((const float4*)(A + (size_t)(l >> 3) * KDIM))[tid];
            uint32_t r0, r1, r2, r3;
            asm("cvt.rna.tf32.f32 %0, %1;" : "=r"(r0) : "f"(v.x));
            asm("cvt.rna.tf32.f32 %0, %1;" : "=r"(r1) : "f"(v.y));
            asm("cvt.rna.tf32.f32 %0, %1;" : "=r"(r2) : "f"(v.z));
            asm("cvt.rna.tf32.f32 %0, %1;" : "=r"(r3) : "f"(v.w));
            const int f = t >> 3;
            const int s4 = (t & 7) << 2;
            char* base = smem + SM_A + (((kb16 << 2) + f) << 9) + (j << 2);
            *(uint32_t*)(base + (((s4 + 0) ^ sw) << 4)) = r0;
            *(uint32_t*)(base + (((s4 + 1) ^ sw) << 4)) = r1;
            *(uint32_t*)(base + (((s4 + 2) ^ sw) << 4)) = r2;
            *(uint32_t*)(base + (((s4 + 3) ^ sw) << 4)) = r3;
        }
    }

    // ---- continuous 256-chunk pipeline across 8 tiles ----
    float acc[4][4] = {};
    const int rlo = (w << 4) + (lane >> 2);       // weight row in tile, 0..127
    const uint32_t swz = ((lane >> 2) & 7) << 4;  // (rlo&7)*16
    float* stg = (float*)(smem + OFF_STG);        // 32 x 132 floats

    for (int i = 0; i < CHUNKS_TOTAL; ++i) {
        // wait for chunk i (bounded number of younger groups may be pending)
        if (i < CHUNKS_TOTAL - 2)      asm volatile("cp.async.wait_group 2;" ::: "memory");
        else if (i == CHUNKS_TOTAL - 2) asm volatile("cp.async.wait_group 1;" ::: "memory");
        else                            asm volatile("cp.async.wait_group 0;" ::: "memory");
        __syncthreads();

        // issue chunk i+3 into the stage consumed at iteration i-1
        if (i + STAGES - 1 < CHUNKS_TOTAL) {
            const int c = i + STAGES - 1;
            const int tilec = c >> 5, cc = c & 31;
            const uint32_t stage_base = sb + SM_B + (c & (STAGES - 1)) * STAGE_BYTES;
            #pragma unroll
            for (int q = 0; q < 4; ++q) {
                int id = tid + q * NTHR;
                int row = id >> 3, g = id & 7;
                cpa16(stage_base + row * 128 + ((g * 16) ^ ((row & 7) * 16)),
                      Bsrc + ((size_t)(tilec * MT + row)) * KDIM + cc * CHUNK_K + g * 4);
            }
            asm volatile("cp.async.commit_group;" ::: "memory");
        }

        // compute chunk i from stage i&3
        {
            const int c32 = i & 31;
            const char* stgp = smem + SM_B + (i & (STAGES - 1)) * STAGE_BYTES + rlo * 128;
            #pragma unroll
            for (int kb = 0; kb < 2; ++kb) {
                const int kb16 = c32 * 2 + kb;
                uint4 bq[4];
                #pragma unroll
                for (int f = 0; f < 4; ++f)
                    bq[f] = *(const uint4*)(smem + SM_A +
                            ((((kb16 << 2) + f) << 5) + (lane ^ (kb16 & 7))) * 16);
                #pragma unroll
                for (int d8 = 0; d8 < 2; ++d8) {
                    const int cb = (kb << 4) + (d8 << 3) + (lane & 3);
                    const uint32_t x0 = ((uint32_t)(cb << 2)) ^ swz;
                    const uint32_t x1 = ((uint32_t)((cb + 4) << 2)) ^ swz;
                    uint32_t a0 = *(const uint32_t*)(stgp + x0);
                    uint32_t a1 = *(const uint32_t*)(stgp + 1024 + x0);
                    uint32_t a2 = *(const uint32_t*)(stgp + x1);
                    uint32_t a3 = *(const uint32_t*)(stgp + 1024 + x1);
                    if (d8 == 0) {
                        MMA_TF32(acc[0], a0, a1, a2, a3, bq[0].x, bq[0].y);
                        MMA_TF32(acc[1], a0, a1, a2, a3, bq[1].x, bq[1].y);
                        MMA_TF32(acc[2], a0, a1, a2, a3, bq[2].x, bq[2].y);
                        MMA_TF32(acc[3], a0, a1, a2, a3, bq[3].x, bq[3].y);
                    } else {
                        MMA_TF32(acc[0], a0, a1, a2, a3, bq[0].z, bq[0].w);
                        MMA_TF32(acc[1], a0, a1, a2, a3, bq[1].z, bq[1].w);
                        MMA_TF32(acc[2], a0, a1, a2, a3, bq[2].z, bq[2].w);
                        MMA_TF32(acc[3], a0, a1, a2, a3, bq[3].z, bq[3].w);
                    }
                }
            }
        }

        // tile boundary: epilogue (loads for future chunks remain in flight)
        if ((i & 31) == 31) {
            const int tile = i >> 5;
            const int nbase = half * (TILES_PER_CTA * MT) + tile * MT;
            const float bv0 = bias[e * NDIM + nbase + rlo];
            const float bv1 = bias[e * NDIM + nbase + rlo + 8];
            #pragma unroll
            for (int f = 0; f < 4; ++f) {
                const int t0 = (f << 3) + ((lane & 3) << 1);
                const float w0 = lw_s[t0], w1 = lw_s[t0 + 1];
                stg[t0 * 132 + rlo]           = (acc[f][0] + bv0) * w0;
                stg[(t0 + 1) * 132 + rlo]     = (acc[f][1] + bv0) * w1;
                stg[t0 * 132 + rlo + 8]       = (acc[f][2] + bv1) * w0;
                stg[(t0 + 1) * 132 + rlo + 8] = (acc[f][3] + bv1) * w1;
            }
            __syncthreads();
            #pragma unroll 4
            for (int idx = tid; idx < CAP * MT; idx += NTHR) {
                const int t = idx >> 7, n = idx & 127;
                out[(size_t)li_s[t] * NDIM + nbase + n] = stg[t * 132 + n];
            }
            #pragma unroll
            for (int f = 0; f < 4; ++f)
                #pragma unroll
                for (int cidx = 0; cidx < 4; ++cidx)
                    acc[f][cidx] = 0.0f;
            // no extra sync needed: next loop-top __syncthreads orders stg reuse
        }
    }
}

// ---------------- host launch ----------------
extern "C" void kernel_launch(void* const* d_in, const int* in_sizes, int n_in,
                              void* d_out, int out_size) {
    const float* A    = (const float*)d_in[0];
    const float* B    = (const float*)d_in[1];
    const float* bias = (const float*)d_in[2];
    const float* tw   = (const float*)d_in[3];
    const int*   ids  = (const int*)d_in[4];
    float*       out  = (float*)d_out;

    static bool attr_set = false;
    if (!attr_set) {
        cudaFuncSetAttribute(moe_gemm_kernel,
                             cudaFuncAttributeMaxDynamicSharedMemorySize, SMEM_TOTAL);
        attr_set = true;
    }

    moe_gemm_kernel<<<NCTA, NTHR, SMEM_TOTAL>>>(A, B, bias, tw, ids, out);
}